// round 1
// baseline (speedup 1.0000x reference)
#include <cuda_runtime.h>
#include <cuda_bf16.h>
#include <cstdint>

// Problem constants (BuseE): N_ENT=200000, N_REL=500, DIM=64, B=1024, NC=1024
#define N_ENT 200000
#define BQ    1024
#define NC    1024
#define MARGIN 9.0f
#define EPS 1e-15f

// ---------------- device scratch (allocation-free) ----------------
// tail rows as bf16: 200000 * 64 * 2B = 25.6MB, stored as uint2 (4 bf16 each)
__device__ uint2  g_tail[N_ENT * 16];
// per-entity: {t2 = ||tail||^2, log(max(1-t2,eps)), bias_tail, pad}
__device__ float4 g_tab[N_ENT];
// per-b transformed head (fp32, 64 dims)
__device__ float  g_head[BQ * 64];
// per-b: {A, sig, hh, pad}
__device__ float4 g_rowc[BQ];

// ---------------- kernel 0: per-entity precompute -----------------
// half-warp per entity row: 16 lanes x float4 = 64 dims
__global__ void __launch_bounds__(256) prep_tail_kernel(
    const float* __restrict__ emb, const float* __restrict__ bias_tail)
{
    int row = blockIdx.x * 16 + (threadIdx.x >> 4);
    int sub = threadIdx.x & 15;

    float4 u4 = reinterpret_cast<const float4*>(emb)[row * 16 + sub];
    float p = u4.x * u4.x + u4.y * u4.y + u4.z * u4.z + u4.w * u4.w;
    #pragma unroll
    for (int m = 8; m; m >>= 1) p += __shfl_xor_sync(0xffffffffu, p, m);

    float un = fmaxf(sqrtf(p), EPS);
    float t  = tanhf(un);
    float f  = t / un;

    __nv_bfloat162 b0 = __floats2bfloat162_rn(f * u4.x, f * u4.y);
    __nv_bfloat162 b1 = __floats2bfloat162_rn(f * u4.z, f * u4.w);
    uint2 o;
    o.x = *reinterpret_cast<unsigned int*>(&b0);
    o.y = *reinterpret_cast<unsigned int*>(&b1);
    g_tail[row * 16 + sub] = o;

    if (sub == 0) {
        float t2 = f * f * p;  // == ||expmap0(u)||^2 (matches reference clamping)
        g_tab[row] = make_float4(t2, logf(fmaxf(1.f - t2, EPS)),
                                 bias_tail[row], 0.f);
    }
}

// ---------------- kernel 1: per-b head transform ------------------
__device__ __forceinline__ float wsum32(float v) {
    #pragma unroll
    for (int m = 16; m; m >>= 1) v += __shfl_xor_sync(0xffffffffu, v, m);
    return v;
}

__device__ __forceinline__ float2 expmap0_w(float2 v) {
    float n2 = wsum32(v.x * v.x + v.y * v.y);
    float un = fmaxf(sqrtf(n2), EPS);
    float f  = tanhf(un) / un;
    return make_float2(f * v.x, f * v.y);
}

__device__ __forceinline__ float2 mobius_w(float2 x, float2 y) {
    float x2 = wsum32(x.x * x.x + x.y * x.y);
    float y2 = wsum32(y.x * y.x + y.y * y.y);
    float xy = wsum32(x.x * y.x + x.y * y.y);
    float a   = 1.f + 2.f * xy + y2;
    float bq  = 1.f - x2;
    float den = fmaxf(1.f + 2.f * xy + x2 * y2, EPS);
    float inv = 1.f / den;
    return make_float2((a * x.x + bq * y.x) * inv,
                       (a * x.y + bq * y.y) * inv);
}

__global__ void __launch_bounds__(256) prep_head_kernel(
    const int* __restrict__ u_idx, const int* __restrict__ r_idx,
    const float* __restrict__ emb, const float* __restrict__ rel_diag,
    const float* __restrict__ rb1, const float* __restrict__ rb2,
    const float* __restrict__ bias_head, const float* __restrict__ sigma)
{
    int b    = blockIdx.x * 8 + (threadIdx.x >> 5);
    int lane = threadIdx.x & 31;
    int u = u_idx[b];
    int r = r_idx[b];

    float2 h  = expmap0_w(reinterpret_cast<const float2*>(emb + (size_t)u * 64)[lane]);
    float2 y1 = expmap0_w(reinterpret_cast<const float2*>(rb1 + (size_t)r * 64)[lane]);
    h = mobius_w(h, y1);

    float2 g  = reinterpret_cast<const float2*>(rel_diag + (size_t)r * 64)[lane];
    float gn  = fmaxf(sqrtf(g.x * g.x + g.y * g.y), EPS);
    float gx = g.x / gn, gy = g.y / gn;
    float2 rot = make_float2(gx * h.x - gy * h.y, gy * h.x + gx * h.y);

    float2 y2 = expmap0_w(reinterpret_cast<const float2*>(rb2 + (size_t)r * 64)[lane]);
    h = mobius_w(rot, y2);

    float hh = wsum32(h.x * h.x + h.y * h.y);
    reinterpret_cast<float2*>(g_head + b * 64)[lane] = h;

    if (lane == 0) {
        float sg = 1.f / (1.f + expf(-sigma[r]));
        float A  = MARGIN + bias_head[u]
                 + (1.f - sg) * logf(fmaxf(1.f - hh, EPS));
        g_rowc[b] = make_float4(A, sg, hh, 0.f);
    }
}

// ---------------- kernel 2: scoring (hot loop) --------------------
// One block per b-row (256 thr). Half-warp per output element; each warp
// computes 2 elements per step, unrolled 2x (4 rows in flight per warp).
__device__ __forceinline__ float dot4_bf16(float4 h4, uint2 e) {
    __nv_bfloat162 p0 = *reinterpret_cast<__nv_bfloat162*>(&e.x);
    __nv_bfloat162 p1 = *reinterpret_cast<__nv_bfloat162*>(&e.y);
    float2 fa = __bfloat1622float2(p0);
    float2 fb = __bfloat1622float2(p1);
    return fmaf(h4.x, fa.x, fmaf(h4.y, fa.y, fmaf(h4.z, fb.x, h4.w * fb.y)));
}

__global__ void __launch_bounds__(256) score_kernel(
    const int* __restrict__ v_idx, float* __restrict__ out)
{
    int b    = blockIdx.x;
    int lane = threadIdx.x & 31;
    int w    = threadIdx.x >> 5;    // 0..7
    int sub  = lane & 15;
    int half = lane >> 4;

    float4 h4 = reinterpret_cast<const float4*>(g_head + b * 64)[sub];
    float4 rc = g_rowc[b];          // {A, sig, hh, _}

    const int* vrow = v_idx + (size_t)b * NC;
    float*     orow = out   + (size_t)b * NC;

    for (int i = 0; i < NC; i += 32) {
        int c0 = i + 4 * w + half;
        int c1 = c0 + 2;
        int v0 = __ldg(vrow + c0);
        int v1 = __ldg(vrow + c1);

        uint2 e0 = g_tail[v0 * 16 + sub];
        uint2 e1 = g_tail[v1 * 16 + sub];
        float4 t0 = g_tab[v0];
        float4 t1 = g_tab[v1];

        float d0 = dot4_bf16(h4, e0);
        float d1 = dot4_bf16(h4, e1);
        #pragma unroll
        for (int m = 8; m; m >>= 1) {
            d0 += __shfl_xor_sync(0xffffffffu, d0, m);
            d1 += __shfl_xor_sync(0xffffffffu, d1, m);
        }

        float num0 = rc.z + t0.x - 2.f * d0;
        float num1 = rc.z + t1.x - 2.f * d1;
        float r0 = rc.x - __logf(fmaxf(num0, EPS)) + rc.y * t0.y + t0.z;
        float r1 = rc.x - __logf(fmaxf(num1, EPS)) + rc.y * t1.y + t1.z;

        if (sub == 0) {
            orow[c0] = r0;
            orow[c1] = r1;
        }
    }
}

// ---------------- launch ------------------------------------------
extern "C" void kernel_launch(void* const* d_in, const int* in_sizes, int n_in,
                              void* d_out, int out_size)
{
    const int*   u_idx     = (const int*)  d_in[0];
    const int*   r_idx     = (const int*)  d_in[1];
    const int*   v_idx     = (const int*)  d_in[2];
    const float* emb       = (const float*)d_in[3];
    const float* rel_diag  = (const float*)d_in[4];
    const float* rb1       = (const float*)d_in[5];
    const float* rb2       = (const float*)d_in[6];
    const float* bias_head = (const float*)d_in[7];
    const float* bias_tail = (const float*)d_in[8];
    const float* sigma     = (const float*)d_in[9];
    float* out = (float*)d_out;

    // 200000 rows / 16 rows-per-block = 12500 blocks (exact)
    prep_tail_kernel<<<N_ENT / 16, 256>>>(emb, bias_tail);
    // 1024 heads / 8 warps-per-block = 128 blocks
    prep_head_kernel<<<BQ / 8, 256>>>(u_idx, r_idx, emb, rel_diag, rb1, rb2,
                                      bias_head, sigma);
    // one block per b-row
    score_kernel<<<BQ, 256>>>(v_idx, out);
}

// round 2
// speedup vs baseline: 1.3353x; 1.3353x over previous
#include <cuda_runtime.h>
#include <cuda_bf16.h>
#include <cstdint>

// Problem constants (BuseE): N_ENT=200000, N_REL=500, DIM=64, B=1024, NC=1024
#define N_ENT 200000
#define BQ    1024
#define NC    1024
#define MARGIN 9.0f
#define EPS 1e-15f

#define TAIL_BLOCKS (N_ENT / 32)   // 6250 (32 rows / 256-thr block)
#define HEAD_BLOCKS (BQ / 8)       // 128  (8 heads / 256-thr block)

// ---------------- device scratch (allocation-free) ----------------
// tail rows as bf16: 200000 * 64 * 2B = 25.6MB, row = 8 x uint4 (16B each)
__device__ uint4  g_tail[N_ENT * 8];
// per-entity: {t2 = ||tail||^2, log(max(1-t2,eps)), bias_tail, pad}
__device__ float4 g_tab[N_ENT];
// per-b transformed head (fp32, 64 dims)
__device__ float  g_head[BQ * 64];
// per-b: {A, sig, hh, pad}
__device__ float4 g_rowc[BQ];

// ---------------- fast math helpers -------------------------------
__device__ __forceinline__ float tanh_approx(float x) {
    float r;
    asm("tanh.approx.f32 %0, %1;" : "=f"(r) : "f"(x));
    return r;
}

__device__ __forceinline__ float wsum32(float v) {
    #pragma unroll
    for (int m = 16; m; m >>= 1) v += __shfl_xor_sync(0xffffffffu, v, m);
    return v;
}

// ---------------- head transform primitives (warp-per-row) --------
__device__ __forceinline__ float2 expmap0_w(float2 v) {
    float n2   = wsum32(v.x * v.x + v.y * v.y);
    float rinv = rsqrtf(fmaxf(n2, 1e-36f));
    float un   = fmaxf(n2 * rinv, EPS);      // = max(||v||, eps)
    float f    = tanh_approx(un) * rinv;     // tanh(un)/un
    return make_float2(f * v.x, f * v.y);
}

__device__ __forceinline__ float2 mobius_w(float2 x, float2 y) {
    float x2 = wsum32(x.x * x.x + x.y * x.y);
    float y2 = wsum32(y.x * y.x + y.y * y.y);
    float xy = wsum32(x.x * y.x + x.y * y.y);
    float a   = 1.f + 2.f * xy + y2;
    float bq  = 1.f - x2;
    float inv = 1.f / fmaxf(1.f + 2.f * xy + x2 * y2, EPS);
    return make_float2((a * x.x + bq * y.x) * inv,
                       (a * x.y + bq * y.y) * inv);
}

// ---------------- fused prep kernel -------------------------------
// blocks [0, TAIL_BLOCKS)                : per-entity tail precompute
// blocks [TAIL_BLOCKS, +HEAD_BLOCKS)     : per-b head transform
__global__ void __launch_bounds__(256) prep_kernel(
    const int* __restrict__ u_idx, const int* __restrict__ r_idx,
    const float* __restrict__ emb, const float* __restrict__ rel_diag,
    const float* __restrict__ rb1, const float* __restrict__ rb2,
    const float* __restrict__ bias_head, const float* __restrict__ bias_tail,
    const float* __restrict__ sigma)
{
    if (blockIdx.x < TAIL_BLOCKS) {
        // ---- tail path: 8 lanes per entity row (32 rows / block) ----
        int row = blockIdx.x * 32 + (threadIdx.x >> 3);
        int s   = threadIdx.x & 7;

        const float4* e4 = reinterpret_cast<const float4*>(emb) + (size_t)row * 16;
        float4 a = e4[s * 2];
        float4 c = e4[s * 2 + 1];
        float p = a.x * a.x + a.y * a.y + a.z * a.z + a.w * a.w
                + c.x * c.x + c.y * c.y + c.z * c.z + c.w * c.w;
        #pragma unroll
        for (int m = 4; m; m >>= 1) p += __shfl_xor_sync(0xffffffffu, p, m);

        float rinv = rsqrtf(fmaxf(p, 1e-36f));
        float un   = fmaxf(p * rinv, EPS);
        float f    = tanh_approx(un) * rinv;        // tanh(||u||)/||u||

        __nv_bfloat162 b0 = __floats2bfloat162_rn(f * a.x, f * a.y);
        __nv_bfloat162 b1 = __floats2bfloat162_rn(f * a.z, f * a.w);
        __nv_bfloat162 b2 = __floats2bfloat162_rn(f * c.x, f * c.y);
        __nv_bfloat162 b3 = __floats2bfloat162_rn(f * c.z, f * c.w);
        uint4 o;
        o.x = *reinterpret_cast<unsigned int*>(&b0);
        o.y = *reinterpret_cast<unsigned int*>(&b1);
        o.z = *reinterpret_cast<unsigned int*>(&b2);
        o.w = *reinterpret_cast<unsigned int*>(&b3);
        g_tail[(size_t)row * 8 + s] = o;

        if (s == 0) {
            float t  = tanh_approx(un);
            float t2 = t * t;                        // ||expmap0(u)||^2
            g_tab[row] = make_float4(t2, __logf(fmaxf(1.f - t2, EPS)),
                                     bias_tail[row], 0.f);
        }
    } else {
        // ---- head path: 1 warp per b-row (8 rows / block) ----
        int b    = (blockIdx.x - TAIL_BLOCKS) * 8 + (threadIdx.x >> 5);
        int lane = threadIdx.x & 31;
        int u = u_idx[b];
        int r = r_idx[b];

        float2 h  = expmap0_w(reinterpret_cast<const float2*>(emb + (size_t)u * 64)[lane]);
        float2 y1 = expmap0_w(reinterpret_cast<const float2*>(rb1 + (size_t)r * 64)[lane]);
        h = mobius_w(h, y1);

        float2 g  = reinterpret_cast<const float2*>(rel_diag + (size_t)r * 64)[lane];
        float gri = rsqrtf(fmaxf(g.x * g.x + g.y * g.y, 1e-36f));
        float gx = g.x * gri, gy = g.y * gri;
        float2 rot = make_float2(gx * h.x - gy * h.y, gy * h.x + gx * h.y);

        float2 y2 = expmap0_w(reinterpret_cast<const float2*>(rb2 + (size_t)r * 64)[lane]);
        h = mobius_w(rot, y2);

        float hh = wsum32(h.x * h.x + h.y * h.y);
        reinterpret_cast<float2*>(g_head + b * 64)[lane] = h;

        if (lane == 0) {
            float sg = 1.f / (1.f + __expf(-sigma[r]));
            float A  = MARGIN + bias_head[u]
                     + (1.f - sg) * __logf(fmaxf(1.f - hh, EPS));
            g_rowc[b] = make_float4(A, sg, hh, 0.f);
        }
    }
}

// ---------------- scoring (hot loop) ------------------------------
// One block per b-row (256 thr). 8-lane group per output element:
// each lane loads one uint4 (8 bf16 dims), 3-level shuffle reduce.
// 4 elements per warp per slot, 2 slots per iteration (unrolled).
__device__ __forceinline__ float dot8(float4 ha, float4 hb, uint4 e) {
    float2 f0 = __bfloat1622float2(*reinterpret_cast<__nv_bfloat162*>(&e.x));
    float2 f1 = __bfloat1622float2(*reinterpret_cast<__nv_bfloat162*>(&e.y));
    float2 f2 = __bfloat1622float2(*reinterpret_cast<__nv_bfloat162*>(&e.z));
    float2 f3 = __bfloat1622float2(*reinterpret_cast<__nv_bfloat162*>(&e.w));
    float d = ha.x * f0.x;
    d = fmaf(ha.y, f0.y, d);
    d = fmaf(ha.z, f1.x, d);
    d = fmaf(ha.w, f1.y, d);
    d = fmaf(hb.x, f2.x, d);
    d = fmaf(hb.y, f2.y, d);
    d = fmaf(hb.z, f3.x, d);
    d = fmaf(hb.w, f3.y, d);
    return d;
}

__global__ void __launch_bounds__(256) score_kernel(
    const int* __restrict__ v_idx, float* __restrict__ out)
{
    int b    = blockIdx.x;
    int lane = threadIdx.x & 31;
    int w    = threadIdx.x >> 5;   // 0..7
    int g    = lane >> 3;          // group 0..3
    int s    = lane & 7;           // dim-chunk 0..7

    const float4* h4 = reinterpret_cast<const float4*>(g_head + b * 64);
    float4 ha = h4[s * 2];
    float4 hb = h4[s * 2 + 1];
    float4 rc = g_rowc[b];         // {A, sig, hh, _}

    const int* vrow = v_idx + (size_t)b * NC;
    float*     orow = out   + (size_t)b * NC;

    #pragma unroll 2
    for (int i = 0; i < NC; i += 64) {
        int c0 = i + (w << 2) + g;
        int c1 = c0 + 32;
        int v0 = __ldg(vrow + c0);
        int v1 = __ldg(vrow + c1);

        uint4  e0 = g_tail[(size_t)v0 * 8 + s];
        uint4  e1 = g_tail[(size_t)v1 * 8 + s];
        float4 t0 = g_tab[v0];
        float4 t1 = g_tab[v1];

        float d0 = dot8(ha, hb, e0);
        float d1 = dot8(ha, hb, e1);
        #pragma unroll
        for (int m = 4; m; m >>= 1) {
            d0 += __shfl_xor_sync(0xffffffffu, d0, m);
            d1 += __shfl_xor_sync(0xffffffffu, d1, m);
        }

        float num0 = rc.z + t0.x - 2.f * d0;
        float num1 = rc.z + t1.x - 2.f * d1;
        float r0 = rc.x - __logf(fmaxf(num0, EPS)) + fmaf(rc.y, t0.y, t0.z);
        float r1 = rc.x - __logf(fmaxf(num1, EPS)) + fmaf(rc.y, t1.y, t1.z);

        if (s == 0) {
            orow[c0] = r0;
            orow[c1] = r1;
        }
    }
}

// ---------------- launch ------------------------------------------
extern "C" void kernel_launch(void* const* d_in, const int* in_sizes, int n_in,
                              void* d_out, int out_size)
{
    const int*   u_idx     = (const int*)  d_in[0];
    const int*   r_idx     = (const int*)  d_in[1];
    const int*   v_idx     = (const int*)  d_in[2];
    const float* emb       = (const float*)d_in[3];
    const float* rel_diag  = (const float*)d_in[4];
    const float* rb1       = (const float*)d_in[5];
    const float* rb2       = (const float*)d_in[6];
    const float* bias_head = (const float*)d_in[7];
    const float* bias_tail = (const float*)d_in[8];
    const float* sigma     = (const float*)d_in[9];
    float* out = (float*)d_out;

    prep_kernel<<<TAIL_BLOCKS + HEAD_BLOCKS, 256>>>(
        u_idx, r_idx, emb, rel_diag, rb1, rb2, bias_head, bias_tail, sigma);
    score_kernel<<<BQ, 256>>>(v_idx, out);
}

// round 3
// speedup vs baseline: 1.5493x; 1.1602x over previous
#include <cuda_runtime.h>
#include <cuda_bf16.h>
#include <cstdint>

// Problem constants (BuseE): N_ENT=200000, N_REL=500, DIM=64, B=1024, NC=1024
#define N_ENT 200000
#define BQ    1024
#define NC    1024
#define MARGIN 9.0f
#define EPS 1e-15f

#define TAIL_BLOCKS (N_ENT / 32)   // 6250 (32 rows / 256-thr block)
#define HEAD_BLOCKS (BQ / 8)       // 128  (8 heads / 256-thr block)
#define SEGS 4                     // score blocks per b-row
#define CPB (NC / SEGS)            // 256 candidates per score block

// ---------------- device scratch (allocation-free) ----------------
// tail rows as bf16: 200000 * 64 * 2B = 25.6MB, row = 8 x uint4 (16B each)
__device__ uint4  g_tail[N_ENT * 8];
// per-entity: {t2 = ||tail||^2, log(max(1-t2,eps)), bias_tail, pad}
__device__ float4 g_tab[N_ENT];
// per-b transformed head (fp32, 64 dims)
__device__ float  g_head[BQ * 64];
// per-b: {A, sig, hh, pad}
__device__ float4 g_rowc[BQ];

// ---------------- fast math helpers -------------------------------
__device__ __forceinline__ float tanh_approx(float x) {
    float r;
    asm("tanh.approx.f32 %0, %1;" : "=f"(r) : "f"(x));
    return r;
}

__device__ __forceinline__ float wsum32(float v) {
    #pragma unroll
    for (int m = 16; m; m >>= 1) v += __shfl_xor_sync(0xffffffffu, v, m);
    return v;
}

// ---------------- head transform primitives (warp-per-row) --------
__device__ __forceinline__ float2 expmap0_w(float2 v) {
    float n2   = wsum32(v.x * v.x + v.y * v.y);
    float rinv = rsqrtf(fmaxf(n2, 1e-36f));
    float un   = fmaxf(n2 * rinv, EPS);      // = max(||v||, eps)
    float f    = tanh_approx(un) * rinv;     // tanh(un)/un
    return make_float2(f * v.x, f * v.y);
}

__device__ __forceinline__ float2 mobius_w(float2 x, float2 y) {
    float x2 = wsum32(x.x * x.x + x.y * x.y);
    float y2 = wsum32(y.x * y.x + y.y * y.y);
    float xy = wsum32(x.x * y.x + x.y * y.y);
    float a   = 1.f + 2.f * xy + y2;
    float bq  = 1.f - x2;
    float inv = 1.f / fmaxf(1.f + 2.f * xy + x2 * y2, EPS);
    return make_float2((a * x.x + bq * y.x) * inv,
                       (a * x.y + bq * y.y) * inv);
}

// ---------------- fused prep kernel -------------------------------
__global__ void __launch_bounds__(256) prep_kernel(
    const int* __restrict__ u_idx, const int* __restrict__ r_idx,
    const float* __restrict__ emb, const float* __restrict__ rel_diag,
    const float* __restrict__ rb1, const float* __restrict__ rb2,
    const float* __restrict__ bias_head, const float* __restrict__ bias_tail,
    const float* __restrict__ sigma)
{
    if (blockIdx.x < TAIL_BLOCKS) {
        // ---- tail path: 8 lanes per entity row (32 rows / block) ----
        int row = blockIdx.x * 32 + (threadIdx.x >> 3);
        int s   = threadIdx.x & 7;

        const float4* e4 = reinterpret_cast<const float4*>(emb) + (size_t)row * 16;
        float4 a = e4[s * 2];
        float4 c = e4[s * 2 + 1];
        float p = a.x * a.x + a.y * a.y + a.z * a.z + a.w * a.w
                + c.x * c.x + c.y * c.y + c.z * c.z + c.w * c.w;
        #pragma unroll
        for (int m = 4; m; m >>= 1) p += __shfl_xor_sync(0xffffffffu, p, m);

        float rinv = rsqrtf(fmaxf(p, 1e-36f));
        float un   = fmaxf(p * rinv, EPS);
        float f    = tanh_approx(un) * rinv;        // tanh(||u||)/||u||

        __nv_bfloat162 b0 = __floats2bfloat162_rn(f * a.x, f * a.y);
        __nv_bfloat162 b1 = __floats2bfloat162_rn(f * a.z, f * a.w);
        __nv_bfloat162 b2 = __floats2bfloat162_rn(f * c.x, f * c.y);
        __nv_bfloat162 b3 = __floats2bfloat162_rn(f * c.z, f * c.w);
        uint4 o;
        o.x = *reinterpret_cast<unsigned int*>(&b0);
        o.y = *reinterpret_cast<unsigned int*>(&b1);
        o.z = *reinterpret_cast<unsigned int*>(&b2);
        o.w = *reinterpret_cast<unsigned int*>(&b3);
        g_tail[(size_t)row * 8 + s] = o;

        if (s == 0) {
            float t  = tanh_approx(un);
            float t2 = t * t;                        // ||expmap0(u)||^2
            g_tab[row] = make_float4(t2, __logf(fmaxf(1.f - t2, EPS)),
                                     bias_tail[row], 0.f);
        }
    } else {
        // ---- head path: 1 warp per b-row (8 rows / block) ----
        int b    = (blockIdx.x - TAIL_BLOCKS) * 8 + (threadIdx.x >> 5);
        int lane = threadIdx.x & 31;
        int u = u_idx[b];
        int r = r_idx[b];

        float2 h  = expmap0_w(reinterpret_cast<const float2*>(emb + (size_t)u * 64)[lane]);
        float2 y1 = expmap0_w(reinterpret_cast<const float2*>(rb1 + (size_t)r * 64)[lane]);
        h = mobius_w(h, y1);

        float2 g  = reinterpret_cast<const float2*>(rel_diag + (size_t)r * 64)[lane];
        float gri = rsqrtf(fmaxf(g.x * g.x + g.y * g.y, 1e-36f));
        float gx = g.x * gri, gy = g.y * gri;
        float2 rot = make_float2(gx * h.x - gy * h.y, gy * h.x + gx * h.y);

        float2 y2 = expmap0_w(reinterpret_cast<const float2*>(rb2 + (size_t)r * 64)[lane]);
        h = mobius_w(rot, y2);

        float hh = wsum32(h.x * h.x + h.y * h.y);
        reinterpret_cast<float2*>(g_head + b * 64)[lane] = h;

        if (lane == 0) {
            float sg = 1.f / (1.f + __expf(-sigma[r]));
            float A  = MARGIN + bias_head[u]
                     + (1.f - sg) * __logf(fmaxf(1.f - hh, EPS));
            g_rowc[b] = make_float4(A, sg, hh, 0.f);
        }
    }
}

// ---------------- scoring (hot loop) ------------------------------
// 4 blocks per b-row; block = 256 candidates. 8-lane group per output
// element (one 128B row = one L1 line per element). 4 slots in flight
// per warp (16 elements) to hide L2 gather + SHFL latency.
__device__ __forceinline__ float dot8(float4 ha, float4 hb, uint4 e) {
    float2 f0 = __bfloat1622float2(*reinterpret_cast<__nv_bfloat162*>(&e.x));
    float2 f1 = __bfloat1622float2(*reinterpret_cast<__nv_bfloat162*>(&e.y));
    float2 f2 = __bfloat1622float2(*reinterpret_cast<__nv_bfloat162*>(&e.z));
    float2 f3 = __bfloat1622float2(*reinterpret_cast<__nv_bfloat162*>(&e.w));
    float d = ha.x * f0.x;
    d = fmaf(ha.y, f0.y, d);
    d = fmaf(ha.z, f1.x, d);
    d = fmaf(ha.w, f1.y, d);
    d = fmaf(hb.x, f2.x, d);
    d = fmaf(hb.y, f2.y, d);
    d = fmaf(hb.z, f3.x, d);
    d = fmaf(hb.w, f3.y, d);
    return d;
}

__global__ void __launch_bounds__(256) score_kernel(
    const int* __restrict__ v_idx, float* __restrict__ out)
{
    int b    = blockIdx.x >> 2;          // b-row
    int seg  = blockIdx.x & 3;           // candidate segment
    int lane = threadIdx.x & 31;
    int w    = threadIdx.x >> 5;         // warp 0..7
    int g    = lane >> 3;                // group 0..3
    int s    = lane & 7;                 // dim-chunk 0..7

    const float4* h4 = reinterpret_cast<const float4*>(g_head + b * 64);
    float4 ha = h4[s * 2];
    float4 hb = h4[s * 2 + 1];
    float4 rc = g_rowc[b];               // {A, sig, hh, _}

    // warp owns 32 candidates: [cbase, cbase+32)
    int cbase = seg * CPB + w * 32;
    const int* vrow = v_idx + (size_t)b * NC;
    float*     orow = out   + (size_t)b * NC;

    #pragma unroll
    for (int i0 = 0; i0 < 32; i0 += 16) {   // 2 iterations, 4 slots each
        int   c[4], v[4];
        uint4 e[4];
        float4 t[4];
        float d[4];

        #pragma unroll
        for (int k = 0; k < 4; k++) {
            c[k] = cbase + i0 + k * 4 + g;
            v[k] = __ldg(vrow + c[k]);
        }
        #pragma unroll
        for (int k = 0; k < 4; k++) {
            e[k] = g_tail[(size_t)v[k] * 8 + s];
            t[k] = g_tab[v[k]];
        }
        #pragma unroll
        for (int k = 0; k < 4; k++) d[k] = dot8(ha, hb, e[k]);

        #pragma unroll
        for (int m = 4; m; m >>= 1) {
            #pragma unroll
            for (int k = 0; k < 4; k++)
                d[k] += __shfl_xor_sync(0xffffffffu, d[k], m);
        }

        if (s == 0) {
            #pragma unroll
            for (int k = 0; k < 4; k++) {
                float num = rc.z + t[k].x - 2.f * d[k];
                orow[c[k]] = rc.x - __logf(fmaxf(num, EPS))
                           + fmaf(rc.y, t[k].y, t[k].z);
            }
        }
    }
}

// ---------------- launch ------------------------------------------
extern "C" void kernel_launch(void* const* d_in, const int* in_sizes, int n_in,
                              void* d_out, int out_size)
{
    const int*   u_idx     = (const int*)  d_in[0];
    const int*   r_idx     = (const int*)  d_in[1];
    const int*   v_idx     = (const int*)  d_in[2];
    const float* emb       = (const float*)d_in[3];
    const float* rel_diag  = (const float*)d_in[4];
    const float* rb1       = (const float*)d_in[5];
    const float* rb2       = (const float*)d_in[6];
    const float* bias_head = (const float*)d_in[7];
    const float* bias_tail = (const float*)d_in[8];
    const float* sigma     = (const float*)d_in[9];
    float* out = (float*)d_out;

    prep_kernel<<<TAIL_BLOCKS + HEAD_BLOCKS, 256>>>(
        u_idx, r_idx, emb, rel_diag, rb1, rb2, bias_head, bias_tail, sigma);
    score_kernel<<<BQ * SEGS, 256>>>(v_idx, out);
}